// round 7
// baseline (speedup 1.0000x reference)
#include <cuda_runtime.h>
#include <cstdint>

#define NP      32768
#define NB      128
#define NC      6
#define TOPK    400
#define KEEPK   200
#define NTH     1024
#define EQCAP   2048
#define APT     4       // elements per thread in key kernel
#define CONF_TH 0.5f
#define NMS_TH  0.5f
#define BIGF    1.0e9f
#define NEGF    (-1.0e9f)

// scratch keys: 128 * 32768 * 4B = 16 MB (static device array, no runtime alloc)
__device__ static unsigned int g_keys[(size_t)NB * NP];

__device__ __forceinline__ unsigned int fkey(float x) {
    unsigned int u = __float_as_uint(x);
    return (u & 0x80000000u) ? ~u : (u | 0x80000000u);
}
__device__ __forceinline__ float ikey(unsigned int k) {
    unsigned int u = (k & 0x80000000u) ? (k & 0x7fffffffu) : ~k;
    return __uint_as_float(u);
}

// ---------------- kernel A: pure streaming key computation, full occupancy ----------------
__global__ __launch_bounds__(NTH, 2)
void key_kernel(const float* __restrict__ pred) {
    int base = blockIdx.x * (NTH * APT) + threadIdx.x;
#pragma unroll
    for (int j = 0; j < APT; ++j) {
        int i = base + j * NTH;
        float2 cf = *reinterpret_cast<const float2*>(pred + (size_t)i * 6 + 4);
        float sc = fmaxf(cf.x, cf.y);
        float m = (sc > CONF_TH) ? sc : NEGF;
        g_keys[i] = fkey(m);
    }
}

// ---------------- kernel B: per-image selection + NMS ----------------
struct __align__(16) SmemT {
    union __align__(16) {
        struct {
            unsigned int hist[4096];   // 16 KB
            unsigned int sscan[1024];  // 4 KB
        } sel;
        struct { unsigned int key[EQCAP]; unsigned int idx[EQCAP]; } eq;  // 16 KB
        unsigned int sup[TOPK * 16];   // 25.6 KB (13 words used, 16 padded)
    } u;
    unsigned long long sortbuf[512];   // 4 KB
    unsigned int selkey[512];
    unsigned int selidx[512];
    float2 p1[TOPK];                   // (x1,y1)
    float2 p2[TOPK];                   // (x2,y2)
    float  cscore[TOPK];
    float  clabel[TOPK];
    unsigned int keepw[16];
    int s_bin;
    int s_gt;
    unsigned int s_cnt;
    unsigned int s_eq;
};

// All 1024 threads. Finds largest bin d in [0,4096) with
// (count of keys in bins >= d) >= K; returns d and count of keys in bins > d.
__device__ void find_bin(SmemT& s, int K, int& bin_out, int& gt_out) {
    int t = threadIdx.x;
    unsigned int c[4];
    unsigned int sum = 0;
#pragma unroll
    for (int j = 0; j < 4; j++) { c[j] = s.u.sel.hist[4 * t + j]; sum += c[j]; }
    s.u.sel.sscan[t] = sum;
    if (t == 0) s.s_bin = -1;
    __syncthreads();
    for (int off = 1; off < 1024; off <<= 1) {
        unsigned int v = (t + off < 1024) ? s.u.sel.sscan[t + off] : 0u;
        __syncthreads();
        s.u.sel.sscan[t] += v;
        __syncthreads();
    }
    unsigned int after = s.u.sel.sscan[t] - sum;  // sum over threads > t
    unsigned int run = after;
    int best = -1;
    unsigned int bestgt = 0;
#pragma unroll
    for (int j = 3; j >= 0; j--) {
        unsigned int cnt = c[j];
        if (best < 0 && run + cnt >= (unsigned int)K) { best = 4 * t + j; bestgt = run; }
        run += cnt;
    }
    if (best >= 0) atomicMax(&s.s_bin, best);
    __syncthreads();
    if (best >= 0 && best == s.s_bin) s.s_gt = (int)bestgt;
    __syncthreads();
    bin_out = s.s_bin;
    gt_out = s.s_gt;
}

__global__ __launch_bounds__(NTH, 1)
void box_selector_kernel(const float* __restrict__ pred,
                         const float* __restrict__ priors,
                         float* __restrict__ out) {
    __shared__ SmemT s;
    const int t = threadIdx.x;
    const int b = blockIdx.x;
    const float* pb = pred + (size_t)b * NP * NC;
    const unsigned int* keys = g_keys + (size_t)b * NP;

    // ---------- hist from precomputed keys (coalesced uint4, MLP 8) ----------
    for (int i = t; i < 4096; i += NTH) s.u.sel.hist[i] = 0;
    __syncthreads();
    {
        const uint4* keys4 = reinterpret_cast<const uint4*>(keys);
#pragma unroll
        for (int j = 0; j < (NP / 4) / NTH; ++j) {
            uint4 kv = keys4[t + j * NTH];
            unsigned int kk[4] = {kv.x, kv.y, kv.z, kv.w};
#pragma unroll
            for (int l = 0; l < 4; ++l) {
                unsigned int bin = kk[l] >> 20;
                unsigned int mm = __match_any_sync(0xffffffffu, bin);
                int leader = __ffs(mm) - 1;
                if ((t & 31) == leader) atomicAdd(&s.u.sel.hist[bin], (unsigned int)__popc(mm));
            }
        }
    }
    __syncthreads();
    int d1, g1;
    find_bin(s, TOPK, d1, g1);
    int k1 = TOPK - g1;

    // ---------- merged scan (L2-hot): gather >d1 bins, compact ==d1 bin ----------
    if (t == 0) { s.s_cnt = 0; s.s_eq = 0; }
    __syncthreads();
    {
        const uint4* keys4 = reinterpret_cast<const uint4*>(keys);
        for (int n4 = t; n4 < NP / 4; n4 += NTH) {
            uint4 kv = keys4[n4];
            int base = n4 * 4;
            unsigned int kk[4] = {kv.x, kv.y, kv.z, kv.w};
#pragma unroll
            for (int l = 0; l < 4; ++l) {
                unsigned int k = kk[l];
                int top = (int)(k >> 20);
                if (top > d1) {
                    unsigned int p = atomicAdd(&s.s_cnt, 1u);
                    s.selkey[p] = k;
                    s.selidx[p] = (unsigned int)(base + l);
                } else if (top == d1) {
                    unsigned int e = atomicAdd(&s.s_eq, 1u);
                    if (e < EQCAP) { s.u.eq.key[e] = k; s.u.eq.idx[e] = (unsigned int)(base + l); }
                }
            }
        }
    }
    __syncthreads();
    int eqcnt = (int)s.s_eq;

    if (eqcnt <= EQCAP) {
        // exact ranking of pivot-bin entries (key desc, idx asc); take top k1
        for (int bb = 0; bb < eqcnt; bb += NTH) {
            int me = bb + t;
            bool act = me < eqcnt;
            unsigned int mk = 0, mi = 0;
            if (act) { mk = s.u.eq.key[me]; mi = s.u.eq.idx[me]; }
            int rank = 0;
            for (int j = 0; j < eqcnt; ++j) {
                unsigned int kj = s.u.eq.key[j];
                unsigned int ij = s.u.eq.idx[j];
                if (act && (kj > mk || (kj == mk && ij < mi))) rank++;
            }
            if (act && rank < k1) { s.selkey[g1 + rank] = mk; s.selidx[g1 + rank] = mi; }
        }
    } else {
        // ---------- fallback: radix refine within bin d1 (rare) ----------
        __syncthreads();
        for (int i = t; i < 4096; i += NTH) s.u.sel.hist[i] = 0;
        __syncthreads();
        for (int n = t; n < NP; n += NTH) {
            unsigned int k = keys[n];
            if ((int)(k >> 20) == d1) atomicAdd(&s.u.sel.hist[(k >> 8) & 0xfffu], 1u);
        }
        __syncthreads();
        int d2, g2;
        find_bin(s, k1, d2, g2);
        int k2 = k1 - g2;
        unsigned int P24 = ((unsigned int)d1 << 12) | (unsigned int)d2;
        __syncthreads();
        for (int i = t; i < 4096; i += NTH) s.u.sel.hist[i] = 0;
        __syncthreads();
        for (int n = t; n < NP; n += NTH) {
            unsigned int k = keys[n];
            if ((k >> 8) == P24) atomicAdd(&s.u.sel.hist[k & 0xffu], 1u);
        }
        __syncthreads();
        int d3, g3;
        find_bin(s, k2, d3, g3);
        int need = k2 - g3;
        unsigned int KP = (P24 << 8) | (unsigned int)d3;
        if (t == 0) s.s_cnt = 0;
        __syncthreads();
        for (int n = t; n < NP; n += NTH) {
            unsigned int k = keys[n];
            if ((int)(k >> 20) == d1 && k > KP) {
                unsigned int p = atomicAdd(&s.s_cnt, 1u);
                s.selkey[g1 + p] = k;
                s.selidx[g1 + p] = (unsigned int)n;
            }
        }
        __syncthreads();
        if (t < 32) {   // equals: lowest `need` indices via ordered ballot
            int taken = 0;
            int slot0 = g1 + (k1 - need);
            for (int base2 = 0; base2 < NP && taken < need; base2 += 32) {
                unsigned int k = keys[base2 + t];
                bool e = (k == KP);
                unsigned int bal = __ballot_sync(0xffffffffu, e);
                int rank = __popc(bal & ((1u << t) - 1u));
                if (e && taken + rank < need) {
                    s.selkey[slot0 + taken + rank] = KP;
                    s.selidx[slot0 + taken + rank] = (unsigned int)(base2 + t);
                }
                taken += __popc(bal);
            }
        }
    }
    __syncthreads();

    // ---------- sort 1: descending (key, then lowest idx) -> exact top_k order ----------
    if (t < 512) {
        unsigned long long v = 0ull;
        if (t < TOPK)
            v = ((unsigned long long)s.selkey[t] << 32) | (unsigned int)(~s.selidx[t]);
        s.sortbuf[t] = v;
    }
    __syncthreads();
    for (int kk = 2; kk <= 512; kk <<= 1) {
        for (int j = kk >> 1; j > 0; j >>= 1) {
            if (t < 512) {
                int ixj = t ^ j;
                if (ixj > t) {
                    unsigned long long a = s.sortbuf[t], c = s.sortbuf[ixj];
                    bool desc = ((t & kk) == 0);
                    bool sw = desc ? (a < c) : (a > c);
                    if (sw) { s.sortbuf[t] = c; s.sortbuf[ixj] = a; }
                }
            }
            __syncthreads();
        }
    }

    // ---------- decode 400 candidates (SoA) ----------
    if (t < 16) s.keepw[t] = (t == 12) ? 0xFFFF0000u : 0u;
    if (t < TOPK) {
        unsigned long long v = s.sortbuf[t];
        unsigned int k = (unsigned int)(v >> 32);
        unsigned int idx = ~(unsigned int)v;
        float sc = ikey(k);
        float4 pr = reinterpret_cast<const float4*>(priors)[idx];
        const float* pp = pb + (size_t)idx * 6;
        float l0 = pp[0], l1 = pp[1], l2 = pp[2], l3 = pp[3];
        float c0 = pp[4], c1 = pp[5];
        float cx = pr.x + l0 * 0.1f * pr.z;
        float cy = pr.y + l1 * 0.1f * pr.w;
        float w  = pr.z * expf(l2 * 0.2f);
        float h  = pr.w * expf(l3 * 0.2f);
        s.p1[t] = make_float2(cx - 0.5f * w, cy - 0.5f * h);
        s.p2[t] = make_float2(cx + 0.5f * w, cy + 0.5f * h);
        s.cscore[t] = sc;
        s.clabel[t] = (c1 > c0) ? 1.0f : 0.0f;
        if (!(sc > CONF_TH)) atomicOr(&s.keepw[t >> 5], 1u << (t & 31));
    }
    __syncthreads();

    // ---------- suppression bit matrix: warp-per-row, lane = j, conflict-free ----------
    {
        int wi = t >> 5;
        int lane = t & 31;
        for (int i = wi; i < TOPK; i += 32) {
            float2 a1 = s.p1[i];   // broadcast
            float2 a2 = s.p2[i];
            float ai = (a2.x - a1.x) * (a2.y - a1.y);
            int w0 = i >> 5;
            if (lane < w0) s.u.sup[i * 16 + lane] = 0u;   // empty lower-triangle words
            for (int word = w0; word < 13; ++word) {
                int j = (word << 5) | lane;
                bool supb = false;
                if (j > i && j < TOPK) {
                    float2 c1 = s.p1[j];
                    float2 c2 = s.p2[j];
                    float iw = fminf(a2.x, c2.x) - fmaxf(a1.x, c1.x);
                    float ih = fminf(a2.y, c2.y) - fmaxf(a1.y, c1.y);
                    iw = fmaxf(iw, 0.0f);
                    ih = fmaxf(ih, 0.0f);
                    float inter = iw * ih;
                    float aj = (c2.x - c1.x) * (c2.y - c1.y);
                    float iou = inter / (ai + aj - inter + 1e-12f);
                    supb = iou > NMS_TH;
                }
                unsigned int bal = __ballot_sync(0xffffffffu, supb);
                if (lane == 0) s.u.sup[i * 16 + word] = bal;
            }
        }
    }
    __syncthreads();

    // ---------- serial greedy NMS reduce (rolled inner loop: small I$ footprint) ----------
    if (t == 0) {
        unsigned int r[13];
#pragma unroll
        for (int w = 0; w < 13; w++) r[w] = s.keepw[w];
        const uint4* sup4 = reinterpret_cast<const uint4*>(s.u.sup);
#pragma unroll
        for (int w = 0; w < 13; w++) {
            int nbb = (w == 12) ? 16 : 32;   // rows 400..415 don't exist
#pragma unroll 1
            for (int bb = 0; bb < nbb; bb++) {
                int i = w * 32 + bb;
                if (!((r[w] >> bb) & 1u)) {
                    uint4 a0 = sup4[i * 4 + 0];
                    uint4 a1 = sup4[i * 4 + 1];
                    uint4 a2 = sup4[i * 4 + 2];
                    uint4 a3 = sup4[i * 4 + 3];
                    r[0]  |= a0.x; r[1]  |= a0.y; r[2]  |= a0.z; r[3]  |= a0.w;
                    r[4]  |= a1.x; r[5]  |= a1.y; r[6]  |= a1.z; r[7]  |= a1.w;
                    r[8]  |= a2.x; r[9]  |= a2.y; r[10] |= a2.z; r[11] |= a2.w;
                    r[12] |= a3.x;
                }
            }
        }
#pragma unroll
        for (int w = 0; w < 13; w++) s.keepw[w] = r[w];
    }
    __syncthreads();

    // ---------- sort 2: ascending (keep ? score : BIG, then position) ----------
    if (t < 512) {
        unsigned long long v = 0xFFFFFFFFFFFFFFFFull;
        if (t < TOPK) {
            bool kp = !((s.keepw[t >> 5] >> (t & 31)) & 1u);
            float skf = kp ? s.cscore[t] : BIGF;
            unsigned int sk = __float_as_uint(skf);
            v = ((unsigned long long)sk << 32) | (unsigned int)t;
        }
        s.sortbuf[t] = v;
    }
    __syncthreads();
    for (int kk = 2; kk <= 512; kk <<= 1) {
        for (int j = kk >> 1; j > 0; j >>= 1) {
            if (t < 512) {
                int ixj = t ^ j;
                if (ixj > t) {
                    unsigned long long a = s.sortbuf[t], c = s.sortbuf[ixj];
                    bool asc = ((t & kk) == 0);
                    bool sw = asc ? (a > c) : (a < c);
                    if (sw) { s.sortbuf[t] = c; s.sortbuf[ixj] = a; }
                }
            }
            __syncthreads();
        }
    }

    // ---------- write output ----------
    if (t < KEEPK) {
        unsigned long long v = s.sortbuf[t];
        int c = (int)(unsigned int)(v & 0xffffffffu);
        bool kp = !((s.keepw[c >> 5] >> (c & 31)) & 1u);
        float* o = out + ((size_t)b * KEEPK + t) * 6;
        if (kp) {
            float2 q1 = s.p1[c];
            float2 q2 = s.p2[c];
            o[0] = s.clabel[c];
            o[1] = s.cscore[c];
            o[2] = q1.x; o[3] = q1.y; o[4] = q2.x; o[5] = q2.y;
        } else {
            o[0] = 0.0f; o[1] = 0.0f; o[2] = 0.0f;
            o[3] = 0.0f; o[4] = 0.0f; o[5] = 0.0f;
        }
    }
}

extern "C" void kernel_launch(void* const* d_in, const int* in_sizes, int n_in,
                              void* d_out, int out_size) {
    const float* pred = (const float*)d_in[0];
    const float* pri  = (const float*)d_in[1];
    if (n_in >= 2 && in_sizes[0] < in_sizes[1]) {
        const float* tmp = pred; pred = pri; pri = tmp;
    }
    float* out = (float*)d_out;
    int gridA = (NB * NP) / (NTH * APT);   // 1024 blocks
    key_kernel<<<gridA, NTH>>>(pred);
    box_selector_kernel<<<NB, NTH>>>(pred, pri, out);
}

// round 8
// speedup vs baseline: 1.1342x; 1.1342x over previous
#include <cuda_runtime.h>
#include <cstdint>

#define NP      32768
#define NB      128
#define NC      6
#define TOPK    400
#define KEEPK   200
#define NTH     1024
#define EQCAP   2048
#define APT     4
#define CONF_TH 0.5f
#define NMS_TH  0.5f
#define BIGF    1.0e9f
#define NEGF    (-1.0e9f)

// global scratch (static arrays, no runtime alloc)
__device__ unsigned int g_keys[(size_t)NB * NP];     // 16 MB
__device__ unsigned int g_hist[(size_t)NB * 4096];   // 2 MB

__device__ __forceinline__ unsigned int fkey(float x) {
    unsigned int u = __float_as_uint(x);
    return (u & 0x80000000u) ? ~u : (u | 0x80000000u);
}
__device__ __forceinline__ float ikey(unsigned int k) {
    unsigned int u = (k & 0x80000000u) ? (k & 0x7fffffffu) : ~k;
    return __uint_as_float(u);
}

// ---------------- kernel A: streaming keys + per-image histogram ----------------
// 1024 blocks, 4096 elements each => exactly 8 blocks per image (no boundary crossing)
__global__ __launch_bounds__(NTH, 2)
void key_hist_kernel(const float* __restrict__ pred) {
    __shared__ unsigned int h[4096];
    int t = threadIdx.x;
    for (int i = t; i < 4096; i += NTH) h[i] = 0;
    __syncthreads();
    int img = blockIdx.x >> 3;
    int base = blockIdx.x * (NTH * APT) + t;
#pragma unroll
    for (int j = 0; j < APT; ++j) {
        int i = base + j * NTH;
        float2 cf = *reinterpret_cast<const float2*>(pred + (size_t)i * 6 + 4);
        float sc = fmaxf(cf.x, cf.y);
        float m = (sc > CONF_TH) ? sc : NEGF;
        unsigned int k = fkey(m);
        g_keys[i] = k;
        unsigned int bin = k >> 20;
        unsigned int mm = __match_any_sync(0xffffffffu, bin);
        int leader = __ffs(mm) - 1;
        if ((t & 31) == leader) atomicAdd(&h[bin], (unsigned int)__popc(mm));
    }
    __syncthreads();
    // merge sparse bins to per-image global hist
    for (int i = t; i < 4096; i += NTH) {
        unsigned int v = h[i];
        if (v) atomicAdd(&g_hist[(size_t)img * 4096 + i], v);
    }
}

// ---------------- kernel B: per-image selection + NMS ----------------
struct __align__(16) SmemT {
    union __align__(16) {
        struct {
            unsigned int hist[4096];   // 16 KB
            unsigned int sscan[64];    // warp totals + warp-after
        } sel;
        struct { unsigned int key[EQCAP]; unsigned int idx[EQCAP]; } eq;  // 16 KB
        unsigned long long srt[TOPK];  // 3.2 KB (rank-sorted candidates)
        unsigned int sup[TOPK * 16];   // 25.6 KB (NMS bitmatrix)
    } u;
    unsigned long long sortbuf[512];   // 4 KB
    unsigned int selkey[512];
    unsigned int selidx[512];
    float2 p1[TOPK];
    float2 p2[TOPK];
    float  cscore[TOPK];
    float  clabel[TOPK];
    unsigned int keepw[16];
    int s_bin;
    int s_gt;
    unsigned int s_cnt;
    unsigned int s_eq;
};

// All 1024 threads. Finds largest bin d in [0,4096) with
// (count of keys in bins >= d) >= K; returns d and count of keys in bins > d.
// Barrier-light: warp shuffle suffix scans, 4 barriers total.
__device__ void find_bin(SmemT& s, int K, int& bin_out, int& gt_out) {
    int t = threadIdx.x;
    int lane = t & 31;
    int w = t >> 5;
    unsigned int c[4];
    unsigned int sum = 0;
#pragma unroll
    for (int j = 0; j < 4; j++) { c[j] = s.u.sel.hist[4 * t + j]; sum += c[j]; }
    // warp suffix-inclusive scan (sum over lanes >= lane)
    unsigned int suf = sum;
#pragma unroll
    for (int off = 1; off < 32; off <<= 1) {
        unsigned int v = __shfl_down_sync(0xffffffffu, suf, off);
        if (lane + off < 32) suf += v;
    }
    if (lane == 0) s.u.sel.sscan[w] = suf;   // warp totals
    if (t == 0) s.s_bin = -1;
    __syncthreads();
    if (w == 0) {
        unsigned int wt = s.u.sel.sscan[lane];
        unsigned int ws = wt;
#pragma unroll
        for (int off = 1; off < 32; off <<= 1) {
            unsigned int v = __shfl_down_sync(0xffffffffu, ws, off);
            if (lane + off < 32) ws += v;
        }
        s.u.sel.sscan[32 + lane] = ws - wt;  // sum over warps > lane
    }
    __syncthreads();
    unsigned int after = (suf - sum) + s.u.sel.sscan[32 + w];  // sum over threads > t
    unsigned int run = after;
    int best = -1;
    unsigned int bestgt = 0;
#pragma unroll
    for (int j = 3; j >= 0; j--) {
        unsigned int cnt = c[j];
        if (best < 0 && run + cnt >= (unsigned int)K) { best = 4 * t + j; bestgt = run; }
        run += cnt;
    }
    if (best >= 0) atomicMax(&s.s_bin, best);
    __syncthreads();
    if (best >= 0 && best == s.s_bin) s.s_gt = (int)bestgt;
    __syncthreads();
    bin_out = s.s_bin;
    gt_out = s.s_gt;
}

__global__ __launch_bounds__(NTH, 1)
void box_selector_kernel(const float* __restrict__ pred,
                         const float* __restrict__ priors,
                         float* __restrict__ out) {
    __shared__ SmemT s;
    const int t = threadIdx.x;
    const int b = blockIdx.x;
    const float* pb = pred + (size_t)b * NP * NC;
    const unsigned int* keys = g_keys + (size_t)b * NP;

    // ---------- load precomputed per-image histogram ----------
    for (int i = t; i < 4096; i += NTH) s.u.sel.hist[i] = g_hist[(size_t)b * 4096 + i];
    __syncthreads();
    int d1, g1;
    find_bin(s, TOPK, d1, g1);
    int k1 = TOPK - g1;

    // ---------- merged scan: gather >d1 bins, compact ==d1 bin ----------
    if (t == 0) { s.s_cnt = 0; s.s_eq = 0; }
    __syncthreads();
    {
        const uint4* keys4 = reinterpret_cast<const uint4*>(keys);
#pragma unroll
        for (int j = 0; j < (NP / 4) / NTH; ++j) {
            int n4 = t + j * NTH;
            uint4 kv = keys4[n4];
            int base = n4 * 4;
            unsigned int kk[4] = {kv.x, kv.y, kv.z, kv.w};
#pragma unroll
            for (int l = 0; l < 4; ++l) {
                unsigned int k = kk[l];
                int top = (int)(k >> 20);
                if (top > d1) {
                    unsigned int p = atomicAdd(&s.s_cnt, 1u);
                    s.selkey[p] = k;
                    s.selidx[p] = (unsigned int)(base + l);
                } else if (top == d1) {
                    unsigned int e = atomicAdd(&s.s_eq, 1u);
                    if (e < EQCAP) { s.u.eq.key[e] = k; s.u.eq.idx[e] = (unsigned int)(base + l); }
                }
            }
        }
    }
    __syncthreads();
    int eqcnt = (int)s.s_eq;

    if (eqcnt <= EQCAP) {
        // exact ranking of pivot-bin entries (key desc, idx asc); take top k1
        for (int bb = 0; bb < eqcnt; bb += NTH) {
            int me = bb + t;
            bool act = me < eqcnt;
            unsigned int mk = 0, mi = 0;
            if (act) { mk = s.u.eq.key[me]; mi = s.u.eq.idx[me]; }
            int rank = 0;
            for (int j = 0; j < eqcnt; ++j) {
                unsigned int kj = s.u.eq.key[j];
                unsigned int ij = s.u.eq.idx[j];
                if (act && (kj > mk || (kj == mk && ij < mi))) rank++;
            }
            if (act && rank < k1) { s.selkey[g1 + rank] = mk; s.selidx[g1 + rank] = mi; }
        }
    } else {
        // ---------- fallback: radix refine within bin d1 (rare) ----------
        __syncthreads();
        for (int i = t; i < 4096; i += NTH) s.u.sel.hist[i] = 0;
        __syncthreads();
        for (int n = t; n < NP; n += NTH) {
            unsigned int k = keys[n];
            if ((int)(k >> 20) == d1) atomicAdd(&s.u.sel.hist[(k >> 8) & 0xfffu], 1u);
        }
        __syncthreads();
        int d2, g2;
        find_bin(s, k1, d2, g2);
        int k2 = k1 - g2;
        unsigned int P24 = ((unsigned int)d1 << 12) | (unsigned int)d2;
        __syncthreads();
        for (int i = t; i < 4096; i += NTH) s.u.sel.hist[i] = 0;
        __syncthreads();
        for (int n = t; n < NP; n += NTH) {
            unsigned int k = keys[n];
            if ((k >> 8) == P24) atomicAdd(&s.u.sel.hist[k & 0xffu], 1u);
        }
        __syncthreads();
        int d3, g3;
        find_bin(s, k2, d3, g3);
        int need = k2 - g3;
        unsigned int KP = (P24 << 8) | (unsigned int)d3;
        if (t == 0) s.s_cnt = 0;
        __syncthreads();
        for (int n = t; n < NP; n += NTH) {
            unsigned int k = keys[n];
            if ((int)(k >> 20) == d1 && k > KP) {
                unsigned int p = atomicAdd(&s.s_cnt, 1u);
                s.selkey[g1 + p] = k;
                s.selidx[g1 + p] = (unsigned int)n;
            }
        }
        __syncthreads();
        if (t < 32) {   // equals: lowest `need` indices via ordered ballot
            int taken = 0;
            int slot0 = g1 + (k1 - need);
            for (int base2 = 0; base2 < NP && taken < need; base2 += 32) {
                unsigned int k = keys[base2 + t];
                bool e = (k == KP);
                unsigned int bal = __ballot_sync(0xffffffffu, e);
                int rank = __popc(bal & ((1u << t) - 1u));
                if (e && taken + rank < need) {
                    s.selkey[slot0 + taken + rank] = KP;
                    s.selidx[slot0 + taken + rank] = (unsigned int)(base2 + t);
                }
                taken += __popc(bal);
            }
        }
    }
    __syncthreads();

    // ---------- sort 1 by ranking: descending (key, then lowest idx) ----------
    if (t < TOPK)
        s.sortbuf[t] = ((unsigned long long)s.selkey[t] << 32) | (unsigned int)(~s.selidx[t]);
    __syncthreads();
    if (t < TOPK) {
        unsigned long long my = s.sortbuf[t];
        int rank = 0;
        for (int j = 0; j < TOPK; ++j) rank += (s.sortbuf[j] > my) ? 1 : 0;
        s.u.srt[rank] = my;     // distinct keys -> permutation
    }
    __syncthreads();

    // ---------- decode 400 candidates (SoA) ----------
    if (t < 16) s.keepw[t] = (t == 12) ? 0xFFFF0000u : 0u;
    if (t < TOPK) {
        unsigned long long v = s.u.srt[t];
        unsigned int k = (unsigned int)(v >> 32);
        unsigned int idx = ~(unsigned int)v;
        float sc = ikey(k);
        float4 pr = reinterpret_cast<const float4*>(priors)[idx];
        const float* pp = pb + (size_t)idx * 6;
        float l0 = pp[0], l1 = pp[1], l2 = pp[2], l3 = pp[3];
        float c0 = pp[4], c1 = pp[5];
        float cx = pr.x + l0 * 0.1f * pr.z;
        float cy = pr.y + l1 * 0.1f * pr.w;
        float w  = pr.z * expf(l2 * 0.2f);
        float h  = pr.w * expf(l3 * 0.2f);
        s.p1[t] = make_float2(cx - 0.5f * w, cy - 0.5f * h);
        s.p2[t] = make_float2(cx + 0.5f * w, cy + 0.5f * h);
        s.cscore[t] = sc;
        s.clabel[t] = (c1 > c0) ? 1.0f : 0.0f;
        if (!(sc > CONF_TH)) atomicOr(&s.keepw[t >> 5], 1u << (t & 31));
    }
    __syncthreads();

    // ---------- suppression bit matrix: warp-per-row, lane = j, conflict-free ----------
    {
        int wi = t >> 5;
        int lane = t & 31;
        for (int i = wi; i < TOPK; i += 32) {
            float2 a1 = s.p1[i];
            float2 a2 = s.p2[i];
            float ai = (a2.x - a1.x) * (a2.y - a1.y);
            int w0 = i >> 5;
            if (lane < w0) s.u.sup[i * 16 + lane] = 0u;
            for (int word = w0; word < 13; ++word) {
                int j = (word << 5) | lane;
                bool supb = false;
                if (j > i && j < TOPK) {
                    float2 c1 = s.p1[j];
                    float2 c2 = s.p2[j];
                    float iw = fminf(a2.x, c2.x) - fmaxf(a1.x, c1.x);
                    float ih = fminf(a2.y, c2.y) - fmaxf(a1.y, c1.y);
                    iw = fmaxf(iw, 0.0f);
                    ih = fmaxf(ih, 0.0f);
                    float inter = iw * ih;
                    float aj = (c2.x - c1.x) * (c2.y - c1.y);
                    float iou = inter / (ai + aj - inter + 1e-12f);
                    supb = iou > NMS_TH;
                }
                unsigned int bal = __ballot_sync(0xffffffffu, supb);
                if (lane == 0) s.u.sup[i * 16 + word] = bal;
            }
        }
    }
    __syncthreads();

    // ---------- serial greedy NMS reduce (rolled inner loop) ----------
    if (t == 0) {
        unsigned int r[13];
#pragma unroll
        for (int w = 0; w < 13; w++) r[w] = s.keepw[w];
        const uint4* sup4 = reinterpret_cast<const uint4*>(s.u.sup);
#pragma unroll
        for (int w = 0; w < 13; w++) {
            int nbb = (w == 12) ? 16 : 32;
#pragma unroll 1
            for (int bb = 0; bb < nbb; bb++) {
                int i = w * 32 + bb;
                if (!((r[w] >> bb) & 1u)) {
                    uint4 a0 = sup4[i * 4 + 0];
                    uint4 a1 = sup4[i * 4 + 1];
                    uint4 a2 = sup4[i * 4 + 2];
                    uint4 a3 = sup4[i * 4 + 3];
                    r[0]  |= a0.x; r[1]  |= a0.y; r[2]  |= a0.z; r[3]  |= a0.w;
                    r[4]  |= a1.x; r[5]  |= a1.y; r[6]  |= a1.z; r[7]  |= a1.w;
                    r[8]  |= a2.x; r[9]  |= a2.y; r[10] |= a2.z; r[11] |= a2.w;
                    r[12] |= a3.x;
                }
            }
        }
#pragma unroll
        for (int w = 0; w < 13; w++) s.keepw[w] = r[w];
    }
    __syncthreads();

    // ---------- sort 2 by ranking: ascending (keep ? score : BIG, then position) ----------
    if (t < TOPK) {
        bool kp = !((s.keepw[t >> 5] >> (t & 31)) & 1u);
        float skf = kp ? s.cscore[t] : BIGF;   // always positive -> uint order = float order
        s.sortbuf[t] = ((unsigned long long)__float_as_uint(skf) << 32) | (unsigned int)t;
    }
    __syncthreads();
    if (t < TOPK) {
        unsigned long long my = s.sortbuf[t];
        int rank = 0;
        for (int j = 0; j < TOPK; ++j) rank += (s.sortbuf[j] < my) ? 1 : 0;
        if (rank < KEEPK) {
            bool kp = !((s.keepw[t >> 5] >> (t & 31)) & 1u);
            float* o = out + ((size_t)b * KEEPK + rank) * 6;
            if (kp) {
                float2 q1 = s.p1[t];
                float2 q2 = s.p2[t];
                o[0] = s.clabel[t];
                o[1] = s.cscore[t];
                o[2] = q1.x; o[3] = q1.y; o[4] = q2.x; o[5] = q2.y;
            } else {
                o[0] = 0.0f; o[1] = 0.0f; o[2] = 0.0f;
                o[3] = 0.0f; o[4] = 0.0f; o[5] = 0.0f;
            }
        }
    }
}

extern "C" void kernel_launch(void* const* d_in, const int* in_sizes, int n_in,
                              void* d_out, int out_size) {
    const float* pred = (const float*)d_in[0];
    const float* pri  = (const float*)d_in[1];
    if (n_in >= 2 && in_sizes[0] < in_sizes[1]) {
        const float* tmp = pred; pred = pri; pri = tmp;
    }
    float* out = (float*)d_out;
    void* hist_ptr = nullptr;
    cudaGetSymbolAddress(&hist_ptr, g_hist);
    cudaMemsetAsync(hist_ptr, 0, (size_t)NB * 4096 * sizeof(unsigned int));
    int gridA = (NB * NP) / (NTH * APT);   // 1024 blocks, 8 per image
    key_hist_kernel<<<gridA, NTH>>>(pred);
    box_selector_kernel<<<NB, NTH>>>(pred, pri, out);
}

// round 9
// speedup vs baseline: 1.2051x; 1.0625x over previous
#include <cuda_runtime.h>
#include <cstdint>

#define NP      32768
#define NB      128
#define NC      6
#define TOPK    400
#define KEEPK   200
#define NTH     1024
#define EQCAP   2048
#define APT     4
#define SUPROWS 416
#define CONF_TH 0.5f
#define NMS_TH  0.5f
#define BIGF    1.0e9f
#define NEGF    (-1.0e9f)

// global scratch (static arrays, no runtime alloc)
__device__ unsigned int g_keys[(size_t)NB * NP];     // 16 MB
__device__ unsigned int g_hist[(size_t)NB * 4096];   // 2 MB

__device__ __forceinline__ unsigned int fkey(float x) {
    unsigned int u = __float_as_uint(x);
    return (u & 0x80000000u) ? ~u : (u | 0x80000000u);
}
__device__ __forceinline__ float ikey(unsigned int k) {
    unsigned int u = (k & 0x80000000u) ? (k & 0x7fffffffu) : ~k;
    return __uint_as_float(u);
}

// ---------------- kernel A: streaming keys + per-image histogram ----------------
__global__ __launch_bounds__(NTH, 2)
void key_hist_kernel(const float* __restrict__ pred) {
    __shared__ unsigned int h[4096];
    int t = threadIdx.x;
    for (int i = t; i < 4096; i += NTH) h[i] = 0;
    __syncthreads();
    int img = blockIdx.x >> 3;
    int base = blockIdx.x * (NTH * APT) + t;
#pragma unroll
    for (int j = 0; j < APT; ++j) {
        int i = base + j * NTH;
        float2 cf = *reinterpret_cast<const float2*>(pred + (size_t)i * 6 + 4);
        float sc = fmaxf(cf.x, cf.y);
        float m = (sc > CONF_TH) ? sc : NEGF;
        unsigned int k = fkey(m);
        g_keys[i] = k;
        unsigned int bin = k >> 20;
        unsigned int mm = __match_any_sync(0xffffffffu, bin);
        int leader = __ffs(mm) - 1;
        if ((t & 31) == leader) atomicAdd(&h[bin], (unsigned int)__popc(mm));
    }
    __syncthreads();
    for (int i = t; i < 4096; i += NTH) {
        unsigned int v = h[i];
        if (v) atomicAdd(&g_hist[(size_t)img * 4096 + i], v);
    }
}

// ---------------- kernel B: per-image selection + NMS ----------------
struct __align__(16) SmemT {
    union __align__(16) {
        struct {
            unsigned int hist[4096];   // 16 KB
            unsigned int sscan[64];
        } sel;
        struct { unsigned int key[EQCAP]; unsigned int idx[EQCAP]; } eq;  // 16 KB
        unsigned int sup[SUPROWS * 16];  // 26.6 KB (13 words used per row)
    } u;
    unsigned long long sortbuf[512];
    unsigned int selkey[512];
    unsigned int selidx[512];
    unsigned long long srt[TOPK];
    float2 p1[TOPK];
    float2 p2[TOPK];
    float  cscore[TOPK];
    float  clabel[TOPK];
    unsigned int keepw[16];
    unsigned int woff[14];
    unsigned int s_mkept;
    int s_bin;
    int s_gt;
    unsigned int s_cnt;
    unsigned int s_eq;
};

__device__ void find_bin(SmemT& s, int K, int& bin_out, int& gt_out) {
    int t = threadIdx.x;
    int lane = t & 31;
    int w = t >> 5;
    unsigned int c[4];
    unsigned int sum = 0;
#pragma unroll
    for (int j = 0; j < 4; j++) { c[j] = s.u.sel.hist[4 * t + j]; sum += c[j]; }
    unsigned int suf = sum;
#pragma unroll
    for (int off = 1; off < 32; off <<= 1) {
        unsigned int v = __shfl_down_sync(0xffffffffu, suf, off);
        if (lane + off < 32) suf += v;
    }
    if (lane == 0) s.u.sel.sscan[w] = suf;
    if (t == 0) s.s_bin = -1;
    __syncthreads();
    if (w == 0) {
        unsigned int wt = s.u.sel.sscan[lane];
        unsigned int ws = wt;
#pragma unroll
        for (int off = 1; off < 32; off <<= 1) {
            unsigned int v = __shfl_down_sync(0xffffffffu, ws, off);
            if (lane + off < 32) ws += v;
        }
        s.u.sel.sscan[32 + lane] = ws - wt;
    }
    __syncthreads();
    unsigned int after = (suf - sum) + s.u.sel.sscan[32 + w];
    unsigned int run = after;
    int best = -1;
    unsigned int bestgt = 0;
#pragma unroll
    for (int j = 3; j >= 0; j--) {
        unsigned int cnt = c[j];
        if (best < 0 && run + cnt >= (unsigned int)K) { best = 4 * t + j; bestgt = run; }
        run += cnt;
    }
    if (best >= 0) atomicMax(&s.s_bin, best);
    __syncthreads();
    if (best >= 0 && best == s.s_bin) s.s_gt = (int)bestgt;
    __syncthreads();
    bin_out = s.s_bin;
    gt_out = s.s_gt;
}

__global__ __launch_bounds__(NTH, 1)
void box_selector_kernel(const float* __restrict__ pred,
                         const float* __restrict__ priors,
                         float* __restrict__ out) {
    __shared__ SmemT s;
    const int t = threadIdx.x;
    const int b = blockIdx.x;
    const float* pb = pred + (size_t)b * NP * NC;
    const unsigned int* keys = g_keys + (size_t)b * NP;

    // ---------- load precomputed per-image histogram ----------
    for (int i = t; i < 4096; i += NTH) s.u.sel.hist[i] = g_hist[(size_t)b * 4096 + i];
    __syncthreads();
    int d1, g1;
    find_bin(s, TOPK, d1, g1);
    int k1 = TOPK - g1;

    // ---------- merged scan: gather >d1 bins, compact ==d1 bin ----------
    if (t == 0) { s.s_cnt = 0; s.s_eq = 0; }
    __syncthreads();
    {
        const uint4* keys4 = reinterpret_cast<const uint4*>(keys);
#pragma unroll
        for (int j = 0; j < (NP / 4) / NTH; ++j) {
            int n4 = t + j * NTH;
            uint4 kv = keys4[n4];
            int base = n4 * 4;
            unsigned int kk[4] = {kv.x, kv.y, kv.z, kv.w};
#pragma unroll
            for (int l = 0; l < 4; ++l) {
                unsigned int k = kk[l];
                int top = (int)(k >> 20);
                if (top > d1) {
                    unsigned int p = atomicAdd(&s.s_cnt, 1u);
                    s.selkey[p] = k;
                    s.selidx[p] = (unsigned int)(base + l);
                } else if (top == d1) {
                    unsigned int e = atomicAdd(&s.s_eq, 1u);
                    if (e < EQCAP) { s.u.eq.key[e] = k; s.u.eq.idx[e] = (unsigned int)(base + l); }
                }
            }
        }
    }
    __syncthreads();
    int eqcnt = (int)s.s_eq;

    if (eqcnt <= EQCAP) {
        // exact ranking of pivot-bin entries — only needed warps iterate
        for (int me = t; me < eqcnt; me += NTH) {
            unsigned int mk = s.u.eq.key[me];
            unsigned int mi = s.u.eq.idx[me];
            int rank = 0;
            for (int j = 0; j < eqcnt; ++j) {
                unsigned int kj = s.u.eq.key[j];
                unsigned int ij = s.u.eq.idx[j];
                if (kj > mk || (kj == mk && ij < mi)) rank++;
            }
            if (rank < k1) { s.selkey[g1 + rank] = mk; s.selidx[g1 + rank] = mi; }
        }
    } else {
        // ---------- fallback: radix refine within bin d1 (rare) ----------
        __syncthreads();
        for (int i = t; i < 4096; i += NTH) s.u.sel.hist[i] = 0;
        __syncthreads();
        for (int n = t; n < NP; n += NTH) {
            unsigned int k = keys[n];
            if ((int)(k >> 20) == d1) atomicAdd(&s.u.sel.hist[(k >> 8) & 0xfffu], 1u);
        }
        __syncthreads();
        int d2, g2;
        find_bin(s, k1, d2, g2);
        int k2 = k1 - g2;
        unsigned int P24 = ((unsigned int)d1 << 12) | (unsigned int)d2;
        __syncthreads();
        for (int i = t; i < 4096; i += NTH) s.u.sel.hist[i] = 0;
        __syncthreads();
        for (int n = t; n < NP; n += NTH) {
            unsigned int k = keys[n];
            if ((k >> 8) == P24) atomicAdd(&s.u.sel.hist[k & 0xffu], 1u);
        }
        __syncthreads();
        int d3, g3;
        find_bin(s, k2, d3, g3);
        int need = k2 - g3;
        unsigned int KP = (P24 << 8) | (unsigned int)d3;
        if (t == 0) s.s_cnt = 0;
        __syncthreads();
        for (int n = t; n < NP; n += NTH) {
            unsigned int k = keys[n];
            if ((int)(k >> 20) == d1 && k > KP) {
                unsigned int p = atomicAdd(&s.s_cnt, 1u);
                s.selkey[g1 + p] = k;
                s.selidx[g1 + p] = (unsigned int)n;
            }
        }
        __syncthreads();
        if (t < 32) {
            int taken = 0;
            int slot0 = g1 + (k1 - need);
            for (int base2 = 0; base2 < NP && taken < need; base2 += 32) {
                unsigned int k = keys[base2 + t];
                bool e = (k == KP);
                unsigned int bal = __ballot_sync(0xffffffffu, e);
                int rank = __popc(bal & ((1u << t) - 1u));
                if (e && taken + rank < need) {
                    s.selkey[slot0 + taken + rank] = KP;
                    s.selidx[slot0 + taken + rank] = (unsigned int)(base2 + t);
                }
                taken += __popc(bal);
            }
        }
    }
    __syncthreads();

    // ---------- sort 1 by ranking: descending (key, then lowest idx) ----------
    if (t < TOPK)
        s.sortbuf[t] = ((unsigned long long)s.selkey[t] << 32) | (unsigned int)(~s.selidx[t]);
    __syncthreads();
    if (t < TOPK) {
        unsigned long long my = s.sortbuf[t];
        int rank = 0;
        for (int j = 0; j < TOPK; ++j) rank += (s.sortbuf[j] > my) ? 1 : 0;
        s.srt[rank] = my;
    }
    __syncthreads();

    // ---------- decode 400 candidates (SoA) ----------
    if (t < 16) s.keepw[t] = (t == 12) ? 0xFFFF0000u : 0u;
    if (t < TOPK) {
        unsigned long long v = s.srt[t];
        unsigned int k = (unsigned int)(v >> 32);
        unsigned int idx = ~(unsigned int)v;
        float sc = ikey(k);
        float4 pr = reinterpret_cast<const float4*>(priors)[idx];
        const float* pp = pb + (size_t)idx * 6;
        float l0 = pp[0], l1 = pp[1], l2 = pp[2], l3 = pp[3];
        float c0 = pp[4], c1 = pp[5];
        float cx = pr.x + l0 * 0.1f * pr.z;
        float cy = pr.y + l1 * 0.1f * pr.w;
        float w  = pr.z * expf(l2 * 0.2f);
        float h  = pr.w * expf(l3 * 0.2f);
        s.p1[t] = make_float2(cx - 0.5f * w, cy - 0.5f * h);
        s.p2[t] = make_float2(cx + 0.5f * w, cy + 0.5f * h);
        s.cscore[t] = sc;
        s.clabel[t] = (c1 > c0) ? 1.0f : 0.0f;
        if (!(sc > CONF_TH)) atomicOr(&s.keepw[t >> 5], 1u << (t & 31));
    }
    __syncthreads();

    // ---------- suppression bit matrix: warp-per-row, margin test (no div) ----------
    {
        int wi = t >> 5;
        int lane = t & 31;
        for (int i = wi; i < TOPK; i += 32) {
            float2 a1 = s.p1[i];
            float2 a2 = s.p2[i];
            float ai = (a2.x - a1.x) * (a2.y - a1.y);
            int w0 = i >> 5;
            for (int word = w0; word < 13; ++word) {
                int j = (word << 5) | lane;
                bool supb = false;
                if (j > i && j < TOPK) {
                    float2 c1 = s.p1[j];
                    float2 c2 = s.p2[j];
                    float iw = fminf(a2.x, c2.x) - fmaxf(a1.x, c1.x);
                    float ih = fminf(a2.y, c2.y) - fmaxf(a1.y, c1.y);
                    iw = fmaxf(iw, 0.0f);
                    ih = fmaxf(ih, 0.0f);
                    float inter = iw * ih;
                    float aj = (c2.x - c1.x) * (c2.y - c1.y);
                    float denom = ai + aj - inter + 1e-12f;
                    float hi = denom * 0.5000100f;
                    float lo = denom * 0.4999900f;
                    if (inter > hi)       supb = true;
                    else if (inter < lo)  supb = false;
                    else                  supb = (inter / denom) > NMS_TH;  // rare exact path
                }
                unsigned int bal = __ballot_sync(0xffffffffu, supb);
                if (lane == 0) s.u.sup[i * 16 + word] = bal;
            }
        }
    }
    __syncthreads();

    // ---------- grouped greedy NMS reduce ----------
#pragma unroll 1
    for (int g = 0; g < 13; ++g) {
        if (t == 0) {
            unsigned int m = s.keepw[g];
            const unsigned int* rowg = &s.u.sup[(g * 32) * 16 + g];
#pragma unroll
            for (int ch = 0; ch < 4; ++ch) {
                unsigned int rr[8];
#pragma unroll
                for (int q = 0; q < 8; ++q) rr[q] = rowg[(ch * 8 + q) * 16];
#pragma unroll
                for (int q = 0; q < 8; ++q) {
                    int bb = ch * 8 + q;
                    if (!((m >> bb) & 1u)) m |= rr[q];
                }
            }
            s.keepw[g] = m;
        }
        __syncthreads();
        {
            int w = g + 1 + (t >> 5);
            if (w < 13) {
                unsigned int m = s.keepw[g];
                int l2 = t & 31;
                unsigned int v = ((m >> l2) & 1u) ? 0u : s.u.sup[(g * 32 + l2) * 16 + w];
#pragma unroll
                for (int off = 16; off; off >>= 1) v |= __shfl_xor_sync(0xffffffffu, v, off);
                if (l2 == 0) s.keepw[w] |= v;
            }
        }
        __syncthreads();
    }

    // ---------- output: kept-only ranking (ascending score, then position) ----------
    if (t == 0) {
        unsigned int acc = 0;
#pragma unroll
        for (int w = 0; w < 13; ++w) { s.woff[w] = acc; acc += (unsigned)__popc(~s.keepw[w]); }
        s.s_mkept = acc;
    }
    __syncthreads();
    bool kp = false;
    if (t < TOPK) {
        kp = !((s.keepw[t >> 5] >> (t & 31)) & 1u);
        if (kp) {
            unsigned int before = (unsigned)__popc(~s.keepw[t >> 5] & ((1u << (t & 31)) - 1u));
            int pos = (int)(s.woff[t >> 5] + before);
            s.sortbuf[pos] = ((unsigned long long)__float_as_uint(s.cscore[t]) << 32) | (unsigned int)t;
        }
    }
    __syncthreads();
    int mk = (int)s.s_mkept;
    if (kp) {
        unsigned long long my = ((unsigned long long)__float_as_uint(s.cscore[t]) << 32) | (unsigned int)t;
        int rank = 0;
        for (int j = 0; j < mk; ++j) rank += (s.sortbuf[j] < my) ? 1 : 0;
        if (rank < KEEPK) {
            float2 q1 = s.p1[t];
            float2 q2 = s.p2[t];
            float* o = out + ((size_t)b * KEEPK + rank) * 6;
            o[0] = s.clabel[t];
            o[1] = s.cscore[t];
            o[2] = q1.x; o[3] = q1.y; o[4] = q2.x; o[5] = q2.y;
        }
    }
    if (t < KEEPK && t >= mk) {
        float* o = out + ((size_t)b * KEEPK + t) * 6;
        o[0] = 0.0f; o[1] = 0.0f; o[2] = 0.0f;
        o[3] = 0.0f; o[4] = 0.0f; o[5] = 0.0f;
    }
}

extern "C" void kernel_launch(void* const* d_in, const int* in_sizes, int n_in,
                              void* d_out, int out_size) {
    const float* pred = (const float*)d_in[0];
    const float* pri  = (const float*)d_in[1];
    if (n_in >= 2 && in_sizes[0] < in_sizes[1]) {
        const float* tmp = pred; pred = pri; pri = tmp;
    }
    float* out = (float*)d_out;
    void* hist_ptr = nullptr;
    cudaGetSymbolAddress(&hist_ptr, g_hist);
    cudaMemsetAsync(hist_ptr, 0, (size_t)NB * 4096 * sizeof(unsigned int));
    int gridA = (NB * NP) / (NTH * APT);
    key_hist_kernel<<<gridA, NTH>>>(pred);
    box_selector_kernel<<<NB, NTH>>>(pred, pri, out);
}

// round 10
// speedup vs baseline: 1.7074x; 1.4168x over previous
#include <cuda_runtime.h>
#include <cstdint>

#define NP      32768
#define NB      128
#define NC      6
#define TOPK    400
#define KEEPK   200
#define NTH     1024
#define EQCAP   2048
#define APT     8
#define SUPROWS 416
#define CONF_TH 0.5f
#define NMS_TH  0.5f
#define BIGF    1.0e9f
#define NEGF    (-1.0e9f)

// global scratch (static arrays, zero-initialized at module load; no runtime alloc)
__device__ unsigned int g_keys[(size_t)NB * NP];     // 16 MB
__device__ unsigned int g_hist[(size_t)NB * 4096];   // 2 MB

__device__ __forceinline__ unsigned int fkey(float x) {
    unsigned int u = __float_as_uint(x);
    return (u & 0x80000000u) ? ~u : (u | 0x80000000u);
}
__device__ __forceinline__ float ikey(unsigned int k) {
    unsigned int u = (k & 0x80000000u) ? (k & 0x7fffffffu) : ~k;
    return __uint_as_float(u);
}

// ---------------- kernel A: streaming keys + per-image histogram ----------------
// 512 blocks, 8192 elements each => exactly 4 blocks per image
__global__ __launch_bounds__(NTH, 2)
void key_hist_kernel(const float* __restrict__ pred) {
    __shared__ unsigned int h[4096];
    int t = threadIdx.x;
    for (int i = t; i < 4096; i += NTH) h[i] = 0;
    __syncthreads();
    int img = blockIdx.x >> 2;
    int base = blockIdx.x * (NTH * APT) + t;
#pragma unroll
    for (int j = 0; j < APT; ++j) {
        int i = base + j * NTH;
        float2 cf = __ldcs(reinterpret_cast<const float2*>(pred + (size_t)i * 6 + 4));
        float sc = fmaxf(cf.x, cf.y);
        float m = (sc > CONF_TH) ? sc : NEGF;
        unsigned int k = fkey(m);
        g_keys[i] = k;
        unsigned int bin = k >> 20;
        unsigned int mm = __match_any_sync(0xffffffffu, bin);
        int leader = __ffs(mm) - 1;
        if ((t & 31) == leader) atomicAdd(&h[bin], (unsigned int)__popc(mm));
    }
    __syncthreads();
    for (int i = t; i < 4096; i += NTH) {
        unsigned int v = h[i];
        if (v) atomicAdd(&g_hist[(size_t)img * 4096 + i], v);
    }
}

// ---------------- kernel B: per-image selection + NMS ----------------
struct __align__(16) SmemT {
    union __align__(16) {
        struct {
            unsigned int hist[4096];   // 16 KB
            unsigned int sscan[64];
        } sel;
        struct { unsigned int key[EQCAP]; unsigned int idx[EQCAP]; } eq;  // 16 KB
        unsigned int sup[SUPROWS * 16];  // 26.6 KB (13 words used per row)
    } u;
    unsigned long long sortbuf[512];
    unsigned int selkey[512];
    unsigned int selidx[512];
    unsigned long long srt[TOPK];
    float2 p1[TOPK];
    float2 p2[TOPK];
    float  cscore[TOPK];
    float  clabel[TOPK];
    unsigned int keepw[16];
    unsigned int woff[14];
    unsigned int s_mkept;
    int s_bin;
    int s_gt;
    unsigned int s_cnt;
    unsigned int s_eq;
};

__device__ void find_bin(SmemT& s, int K, int& bin_out, int& gt_out) {
    int t = threadIdx.x;
    int lane = t & 31;
    int w = t >> 5;
    unsigned int c[4];
    unsigned int sum = 0;
#pragma unroll
    for (int j = 0; j < 4; j++) { c[j] = s.u.sel.hist[4 * t + j]; sum += c[j]; }
    unsigned int suf = sum;
#pragma unroll
    for (int off = 1; off < 32; off <<= 1) {
        unsigned int v = __shfl_down_sync(0xffffffffu, suf, off);
        if (lane + off < 32) suf += v;
    }
    if (lane == 0) s.u.sel.sscan[w] = suf;
    if (t == 0) s.s_bin = -1;
    __syncthreads();
    if (w == 0) {
        unsigned int wt = s.u.sel.sscan[lane];
        unsigned int ws = wt;
#pragma unroll
        for (int off = 1; off < 32; off <<= 1) {
            unsigned int v = __shfl_down_sync(0xffffffffu, ws, off);
            if (lane + off < 32) ws += v;
        }
        s.u.sel.sscan[32 + lane] = ws - wt;
    }
    __syncthreads();
    unsigned int after = (suf - sum) + s.u.sel.sscan[32 + w];
    unsigned int run = after;
    int best = -1;
    unsigned int bestgt = 0;
#pragma unroll
    for (int j = 3; j >= 0; j--) {
        unsigned int cnt = c[j];
        if (best < 0 && run + cnt >= (unsigned int)K) { best = 4 * t + j; bestgt = run; }
        run += cnt;
    }
    if (best >= 0) atomicMax(&s.s_bin, best);
    __syncthreads();
    if (best >= 0 && best == s.s_bin) s.s_gt = (int)bestgt;
    __syncthreads();
    bin_out = s.s_bin;
    gt_out = s.s_gt;
}

__global__ __launch_bounds__(NTH, 1)
void box_selector_kernel(const float* __restrict__ pred,
                         const float* __restrict__ priors,
                         float* __restrict__ out) {
    __shared__ SmemT s;
    const int t = threadIdx.x;
    const int b = blockIdx.x;
    const float* pb = pred + (size_t)b * NP * NC;
    const unsigned int* keys = g_keys + (size_t)b * NP;

    // ---------- load precomputed per-image histogram, then re-zero it for next launch ----------
    for (int i = t; i < 4096; i += NTH) {
        s.u.sel.hist[i] = g_hist[(size_t)b * 4096 + i];
        g_hist[(size_t)b * 4096 + i] = 0u;
    }
    __syncthreads();
    int d1, g1;
    find_bin(s, TOPK, d1, g1);
    int k1 = TOPK - g1;

    // ---------- merged scan: gather >d1 bins, compact ==d1 bin ----------
    if (t == 0) { s.s_cnt = 0; s.s_eq = 0; }
    __syncthreads();
    {
        const uint4* keys4 = reinterpret_cast<const uint4*>(keys);
#pragma unroll
        for (int j = 0; j < (NP / 4) / NTH; ++j) {
            int n4 = t + j * NTH;
            uint4 kv = keys4[n4];
            int base = n4 * 4;
            unsigned int kk[4] = {kv.x, kv.y, kv.z, kv.w};
#pragma unroll
            for (int l = 0; l < 4; ++l) {
                unsigned int k = kk[l];
                int top = (int)(k >> 20);
                if (top > d1) {
                    unsigned int p = atomicAdd(&s.s_cnt, 1u);
                    s.selkey[p] = k;
                    s.selidx[p] = (unsigned int)(base + l);
                } else if (top == d1) {
                    unsigned int e = atomicAdd(&s.s_eq, 1u);
                    if (e < EQCAP) { s.u.eq.key[e] = k; s.u.eq.idx[e] = (unsigned int)(base + l); }
                }
            }
        }
    }
    __syncthreads();
    int eqcnt = (int)s.s_eq;

    if (eqcnt <= EQCAP) {
        for (int me = t; me < eqcnt; me += NTH) {
            unsigned int mk = s.u.eq.key[me];
            unsigned int mi = s.u.eq.idx[me];
            int rank = 0;
            for (int j = 0; j < eqcnt; ++j) {
                unsigned int kj = s.u.eq.key[j];
                unsigned int ij = s.u.eq.idx[j];
                if (kj > mk || (kj == mk && ij < mi)) rank++;
            }
            if (rank < k1) { s.selkey[g1 + rank] = mk; s.selidx[g1 + rank] = mi; }
        }
    } else {
        // ---------- fallback: radix refine within bin d1 (rare) ----------
        __syncthreads();
        for (int i = t; i < 4096; i += NTH) s.u.sel.hist[i] = 0;
        __syncthreads();
        for (int n = t; n < NP; n += NTH) {
            unsigned int k = keys[n];
            if ((int)(k >> 20) == d1) atomicAdd(&s.u.sel.hist[(k >> 8) & 0xfffu], 1u);
        }
        __syncthreads();
        int d2, g2;
        find_bin(s, k1, d2, g2);
        int k2 = k1 - g2;
        unsigned int P24 = ((unsigned int)d1 << 12) | (unsigned int)d2;
        __syncthreads();
        for (int i = t; i < 4096; i += NTH) s.u.sel.hist[i] = 0;
        __syncthreads();
        for (int n = t; n < NP; n += NTH) {
            unsigned int k = keys[n];
            if ((k >> 8) == P24) atomicAdd(&s.u.sel.hist[k & 0xffu], 1u);
        }
        __syncthreads();
        int d3, g3;
        find_bin(s, k2, d3, g3);
        int need = k2 - g3;
        unsigned int KP = (P24 << 8) | (unsigned int)d3;
        if (t == 0) s.s_cnt = 0;
        __syncthreads();
        for (int n = t; n < NP; n += NTH) {
            unsigned int k = keys[n];
            if ((int)(k >> 20) == d1 && k > KP) {
                unsigned int p = atomicAdd(&s.s_cnt, 1u);
                s.selkey[g1 + p] = k;
                s.selidx[g1 + p] = (unsigned int)n;
            }
        }
        __syncthreads();
        if (t < 32) {
            int taken = 0;
            int slot0 = g1 + (k1 - need);
            for (int base2 = 0; base2 < NP && taken < need; base2 += 32) {
                unsigned int k = keys[base2 + t];
                bool e = (k == KP);
                unsigned int bal = __ballot_sync(0xffffffffu, e);
                int rank = __popc(bal & ((1u << t) - 1u));
                if (e && taken + rank < need) {
                    s.selkey[slot0 + taken + rank] = KP;
                    s.selidx[slot0 + taken + rank] = (unsigned int)(base2 + t);
                }
                taken += __popc(bal);
            }
        }
    }
    __syncthreads();

    // ---------- sort 1 by ranking (vectorized, lane-pair split): descending ----------
    if (t < 512) {
        unsigned long long v = 0ull;   // pad: never > any real key
        if (t < TOPK)
            v = ((unsigned long long)s.selkey[t] << 32) | (unsigned int)(~s.selidx[t]);
        s.sortbuf[t] = v;
    }
    __syncthreads();
    if (t < 2 * TOPK) {
        int e = t >> 1;
        int p = t & 1;
        unsigned long long my = s.sortbuf[e];
        const ulonglong2* sb2 = reinterpret_cast<const ulonglong2*>(s.sortbuf) + p * 128;
        int rank = 0;
#pragma unroll 4
        for (int j = 0; j < 128; ++j) {
            ulonglong2 v = sb2[j];
            rank += (v.x > my) ? 1 : 0;
            rank += (v.y > my) ? 1 : 0;
        }
        rank += __shfl_xor_sync(0xffffffffu, rank, 1);
        if (p == 0) s.srt[rank] = my;
    }
    __syncthreads();

    // ---------- decode 400 candidates (SoA) ----------
    if (t < 16) s.keepw[t] = (t == 12) ? 0xFFFF0000u : 0u;
    if (t < TOPK) {
        unsigned long long v = s.srt[t];
        unsigned int k = (unsigned int)(v >> 32);
        unsigned int idx = ~(unsigned int)v;
        float sc = ikey(k);
        float4 pr = reinterpret_cast<const float4*>(priors)[idx];
        const float* pp = pb + (size_t)idx * 6;
        float l0 = pp[0], l1 = pp[1], l2 = pp[2], l3 = pp[3];
        float c0 = pp[4], c1 = pp[5];
        float cx = pr.x + l0 * 0.1f * pr.z;
        float cy = pr.y + l1 * 0.1f * pr.w;
        float w  = pr.z * expf(l2 * 0.2f);
        float h  = pr.w * expf(l3 * 0.2f);
        s.p1[t] = make_float2(cx - 0.5f * w, cy - 0.5f * h);
        s.p2[t] = make_float2(cx + 0.5f * w, cy + 0.5f * h);
        s.cscore[t] = sc;
        s.clabel[t] = (c1 > c0) ? 1.0f : 0.0f;
        if (!(sc > CONF_TH)) atomicOr(&s.keepw[t >> 5], 1u << (t & 31));
    }
    __syncthreads();

    // ---------- suppression bit matrix: warp-per-row, fma margin test (no div) ----------
    {
        int wi = t >> 5;
        int lane = t & 31;
        for (int i = wi; i < TOPK; i += 32) {
            float2 a1 = s.p1[i];
            float2 a2 = s.p2[i];
            float ai = (a2.x - a1.x) * (a2.y - a1.y);
            int w0 = i >> 5;
            for (int word = w0; word < 13; ++word) {
                int j = (word << 5) | lane;
                bool supb = false;
                if (j > i && j < TOPK) {
                    float2 c1 = s.p1[j];
                    float2 c2 = s.p2[j];
                    float iw = fminf(a2.x, c2.x) - fmaxf(a1.x, c1.x);
                    float ih = fminf(a2.y, c2.y) - fmaxf(a1.y, c1.y);
                    iw = fmaxf(iw, 0.0f);
                    ih = fmaxf(ih, 0.0f);
                    float inter = iw * ih;
                    float aj = (c2.x - c1.x) * (c2.y - c1.y);
                    float ssum = ai + aj;
                    // iou > 0.5  <=>  3*inter - ssum > 1e-12 (exact reals)
                    float m = __fmaf_rn(3.0f, inter, -ssum);
                    float tol = 1e-4f * ssum + 1e-20f;
                    if (m > tol)        supb = true;
                    else if (m >= -tol) supb = (inter / (ssum - inter + 1e-12f)) > NMS_TH;
                    // else false
                }
                unsigned int bal = __ballot_sync(0xffffffffu, supb);
                if (lane == 0) s.u.sup[i * 16 + word] = bal;
            }
        }
    }
    __syncthreads();

    // ---------- grouped greedy NMS reduce ----------
#pragma unroll 1
    for (int g = 0; g < 13; ++g) {
        if (t == 0) {
            unsigned int m = s.keepw[g];
            const unsigned int* rowg = &s.u.sup[(g * 32) * 16 + g];
#pragma unroll
            for (int ch = 0; ch < 4; ++ch) {
                unsigned int rr[8];
#pragma unroll
                for (int q = 0; q < 8; ++q) rr[q] = rowg[(ch * 8 + q) * 16];
#pragma unroll
                for (int q = 0; q < 8; ++q) {
                    int bb = ch * 8 + q;
                    if (!((m >> bb) & 1u)) m |= rr[q];
                }
            }
            s.keepw[g] = m;
        }
        __syncthreads();
        {
            int w = g + 1 + (t >> 5);
            if (w < 13) {
                unsigned int m = s.keepw[g];
                int l2 = t & 31;
                unsigned int v = ((m >> l2) & 1u) ? 0u : s.u.sup[(g * 32 + l2) * 16 + w];
#pragma unroll
                for (int off = 16; off; off >>= 1) v |= __shfl_xor_sync(0xffffffffu, v, off);
                if (l2 == 0) s.keepw[w] |= v;
            }
        }
        __syncthreads();
    }

    // ---------- output: kept-only compaction + vectorized pair-split ranking ----------
    if (t == 0) {
        unsigned int acc = 0;
#pragma unroll
        for (int w = 0; w < 13; ++w) { s.woff[w] = acc; acc += (unsigned)__popc(~s.keepw[w]); }
        s.s_mkept = acc;
    }
    __syncthreads();
    int mk = (int)s.s_mkept;
    if (t < TOPK) {
        bool kp = !((s.keepw[t >> 5] >> (t & 31)) & 1u);
        if (kp) {
            unsigned int before = (unsigned)__popc(~s.keepw[t >> 5] & ((1u << (t & 31)) - 1u));
            int pos = (int)(s.woff[t >> 5] + before);
            s.sortbuf[pos] = ((unsigned long long)__float_as_uint(s.cscore[t]) << 32) | (unsigned int)t;
        }
    }
    if (t < 512 && t >= mk) s.sortbuf[t] = 0xFFFFFFFFFFFFFFFFull;  // pad: never < any real
    __syncthreads();
    if (t < 2 * mk) {
        int e = t >> 1;
        int p = t & 1;
        unsigned long long my = s.sortbuf[e];
        const ulonglong2* sb2 = reinterpret_cast<const ulonglong2*>(s.sortbuf) + p * 128;
        int rank = 0;
#pragma unroll 4
        for (int j = 0; j < 128; ++j) {
            ulonglong2 v = sb2[j];
            rank += (v.x < my) ? 1 : 0;
            rank += (v.y < my) ? 1 : 0;
        }
        rank += __shfl_xor_sync(0xffffffffu, rank, 1);
        if (p == 0 && rank < KEEPK) {
            int c = (int)(unsigned int)(my & 0xffffffffu);
            float2 q1 = s.p1[c];
            float2 q2 = s.p2[c];
            float* o = out + ((size_t)b * KEEPK + rank) * 6;
            o[0] = s.clabel[c];
            o[1] = s.cscore[c];
            o[2] = q1.x; o[3] = q1.y; o[4] = q2.x; o[5] = q2.y;
        }
    }
    if (t < KEEPK && t >= mk) {
        float* o = out + ((size_t)b * KEEPK + t) * 6;
        o[0] = 0.0f; o[1] = 0.0f; o[2] = 0.0f;
        o[3] = 0.0f; o[4] = 0.0f; o[5] = 0.0f;
    }
}

extern "C" void kernel_launch(void* const* d_in, const int* in_sizes, int n_in,
                              void* d_out, int out_size) {
    const float* pred = (const float*)d_in[0];
    const float* pri  = (const float*)d_in[1];
    if (n_in >= 2 && in_sizes[0] < in_sizes[1]) {
        const float* tmp = pred; pred = pri; pri = tmp;
    }
    float* out = (float*)d_out;
    int gridA = (NB * NP) / (NTH * APT);   // 512 blocks, 4 per image
    key_hist_kernel<<<gridA, NTH>>>(pred);
    box_selector_kernel<<<NB, NTH>>>(pred, pri, out);
}

// round 12
// speedup vs baseline: 1.8883x; 1.1059x over previous
#include <cuda_runtime.h>
#include <cstdint>

#define NP      32768
#define NB      128
#define NC      6
#define TOPK    400
#define KEEPK   200
#define NTH     1024
#define EQCAP   2048
#define APT     8
#define SUPROWS 416
#define CONF_TH 0.5f
#define NMS_TH  0.5f
#define BIGF    1.0e9f
#define NEGF    (-1.0e9f)

// global scratch (static arrays, zero-initialized at module load; no runtime alloc)
__device__ unsigned int g_keys[(size_t)NB * NP];     // 16 MB
__device__ unsigned int g_hist[(size_t)NB * 4096];   // 2 MB

__device__ __forceinline__ unsigned int fkey(float x) {
    unsigned int u = __float_as_uint(x);
    return (u & 0x80000000u) ? ~u : (u | 0x80000000u);
}
__device__ __forceinline__ float ikey(unsigned int k) {
    unsigned int u = (k & 0x80000000u) ? (k & 0x7fffffffu) : ~k;
    return __uint_as_float(u);
}
__device__ __forceinline__ unsigned long long packci(unsigned int k, unsigned int idx) {
    return ((unsigned long long)k << 32) | (unsigned int)(~idx);
}
// bits j (= w*32+l) with j > i within word w of row i
__device__ __forceinline__ unsigned int rowmask(int i, int w) {
    int wi = i >> 5;
    if (w > wi) return 0xFFFFFFFFu;
    if (w < wi) return 0u;
    return ~(unsigned int)(((unsigned long long)2 << (i & 31)) - 1ull);
}

// ---------------- kernel A: streaming keys + per-image histogram ----------------
__global__ __launch_bounds__(NTH, 2)
void key_hist_kernel(const float* __restrict__ pred) {
    __shared__ unsigned int h[4096];
    int t = threadIdx.x;
    for (int i = t; i < 4096; i += NTH) h[i] = 0;
    __syncthreads();
    int img = blockIdx.x >> 2;
    int base = blockIdx.x * (NTH * APT) + t;
#pragma unroll
    for (int j = 0; j < APT; ++j) {
        int i = base + j * NTH;
        float2 cf = __ldcs(reinterpret_cast<const float2*>(pred + (size_t)i * 6 + 4));
        float sc = fmaxf(cf.x, cf.y);
        float m = (sc > CONF_TH) ? sc : NEGF;
        unsigned int k = fkey(m);
        g_keys[i] = k;
        unsigned int bin = k >> 20;
        unsigned int mm = __match_any_sync(0xffffffffu, bin);
        int leader = __ffs(mm) - 1;
        if ((t & 31) == leader) atomicAdd(&h[bin], (unsigned int)__popc(mm));
    }
    __syncthreads();
    for (int i = t; i < 4096; i += NTH) {
        unsigned int v = h[i];
        if (v) atomicAdd(&g_hist[(size_t)img * 4096 + i], v);
    }
}

// ---------------- kernel B: per-image selection + NMS ----------------
struct __align__(16) SmemT {
    union __align__(16) {
        struct {
            unsigned int hist[4096];   // 16 KB
            unsigned int sscan[64];
        } sel;
        unsigned long long eq[EQCAP];    // 16 KB packed (key<<32|~idx)
        unsigned int sup[SUPROWS * 16];  // 26.6 KB (13 words used per row)
    } u;
    unsigned long long sortbuf[512];
    float4 cbox[SUPROWS];     // rows 400..415 zeroed
    float  carea[SUPROWS];
    float  cscore[TOPK];
    float  clabel[TOPK];
    unsigned int keepw[16];
    unsigned int woff[14];
    unsigned int s_mkept;
    int s_bin;
    int s_gt;
    unsigned int s_cnt;
    unsigned int s_eq;
};

__device__ void find_bin(SmemT& s, int K, int& bin_out, int& gt_out) {
    int t = threadIdx.x;
    int lane = t & 31;
    int w = t >> 5;
    unsigned int c[4];
    unsigned int sum = 0;
#pragma unroll
    for (int j = 0; j < 4; j++) { c[j] = s.u.sel.hist[4 * t + j]; sum += c[j]; }
    unsigned int suf = sum;
#pragma unroll
    for (int off = 1; off < 32; off <<= 1) {
        unsigned int v = __shfl_down_sync(0xffffffffu, suf, off);
        if (lane + off < 32) suf += v;
    }
    if (lane == 0) s.u.sel.sscan[w] = suf;
    if (t == 0) s.s_bin = -1;
    __syncthreads();
    if (w == 0) {
        unsigned int wt = s.u.sel.sscan[lane];
        unsigned int ws = wt;
#pragma unroll
        for (int off = 1; off < 32; off <<= 1) {
            unsigned int v = __shfl_down_sync(0xffffffffu, ws, off);
            if (lane + off < 32) ws += v;
        }
        s.u.sel.sscan[32 + lane] = ws - wt;
    }
    __syncthreads();
    unsigned int after = (suf - sum) + s.u.sel.sscan[32 + w];
    unsigned int run = after;
    int best = -1;
    unsigned int bestgt = 0;
#pragma unroll
    for (int j = 3; j >= 0; j--) {
        unsigned int cnt = c[j];
        if (best < 0 && run + cnt >= (unsigned int)K) { best = 4 * t + j; bestgt = run; }
        run += cnt;
    }
    if (best >= 0) atomicMax(&s.s_bin, best);
    __syncthreads();
    if (best >= 0 && best == s.s_bin) s.s_gt = (int)bestgt;
    __syncthreads();
    bin_out = s.s_bin;
    gt_out = s.s_gt;
}

__global__ __launch_bounds__(NTH, 1)
void box_selector_kernel(const float* __restrict__ pred,
                         const float* __restrict__ priors,
                         float* __restrict__ out) {
    __shared__ SmemT s;
    const int t = threadIdx.x;
    const int b = blockIdx.x;
    const float* pb = pred + (size_t)b * NP * NC;
    const unsigned int* keys = g_keys + (size_t)b * NP;

    // ---------- init + hist load (re-zero global hist for next launch) ----------
    if (t < 16) {
        s.keepw[t] = (t == 12) ? 0xFFFF0000u : 0u;
        s.cbox[TOPK + t] = make_float4(0.f, 0.f, 0.f, 0.f);
        s.carea[TOPK + t] = 0.f;
    }
    for (int i = t; i < 4096; i += NTH) {
        s.u.sel.hist[i] = g_hist[(size_t)b * 4096 + i];
        g_hist[(size_t)b * 4096 + i] = 0u;
    }
    __syncthreads();
    int d1, g1;
    find_bin(s, TOPK, d1, g1);
    int k1 = TOPK - g1;

    // ---------- merged scan: >d1 -> sortbuf (packed), ==d1 -> eq (packed) ----------
    if (t == 0) { s.s_cnt = 0; s.s_eq = 0; }
    __syncthreads();
    {
        const uint4* keys4 = reinterpret_cast<const uint4*>(keys);
#pragma unroll
        for (int j = 0; j < (NP / 4) / NTH; ++j) {
            int n4 = t + j * NTH;
            uint4 kv = keys4[n4];
            int base = n4 * 4;
            unsigned int kk[4] = {kv.x, kv.y, kv.z, kv.w};
#pragma unroll
            for (int l = 0; l < 4; ++l) {
                unsigned int k = kk[l];
                int top = (int)(k >> 20);
                if (top > d1) {
                    unsigned int p = atomicAdd(&s.s_cnt, 1u);
                    s.sortbuf[p] = packci(k, (unsigned int)(base + l));
                } else if (top == d1) {
                    unsigned int e = atomicAdd(&s.s_eq, 1u);
                    if (e < EQCAP) s.u.eq[e] = packci(k, (unsigned int)(base + l));
                }
            }
        }
    }
    __syncthreads();
    int eqcnt = (int)s.s_eq;

    if (eqcnt <= EQCAP) {
        if (t == 0 && (eqcnt & 1) && eqcnt < EQCAP) s.u.eq[eqcnt] = 0ull;  // pad (never > real)
        __syncthreads();
        // vectorized pair-split ranking of eq (desc). WARP-UNIFORM trip count:
        // bound rounded to multiple of NTH so every lane executes every shfl.
        int nvec = (eqcnt + 1) >> 1;
        int hh = (nvec + 1) >> 1;
        int tot = 2 * eqcnt;                       // even
        int tlim = (tot + NTH - 1) / NTH * NTH;    // uniform across block
        for (int tt = t; tt < tlim; tt += NTH) {
            int e = tt >> 1;                        // e <= 2047 < EQCAP
            int p = tt & 1;
            unsigned long long my = s.u.eq[e];      // garbage ok for inactive pairs
            const ulonglong2* e2 = reinterpret_cast<const ulonglong2*>(s.u.eq);
            int j0 = p * hh;
            int j1 = min(nvec, j0 + hh);
            int rank = 0;
            for (int j = j0; j < j1; ++j) {
                ulonglong2 v = e2[j];
                rank += (v.x > my) ? 1 : 0;
                rank += (v.y > my) ? 1 : 0;
            }
            rank += __shfl_xor_sync(0xffffffffu, rank, 1);
            if (tt < tot && p == 0 && rank < k1) s.sortbuf[g1 + rank] = my;
        }
    } else {
        // ---------- fallback: radix refine within bin d1 (rare) ----------
        __syncthreads();
        for (int i = t; i < 4096; i += NTH) s.u.sel.hist[i] = 0;
        __syncthreads();
        for (int n = t; n < NP; n += NTH) {
            unsigned int k = keys[n];
            if ((int)(k >> 20) == d1) atomicAdd(&s.u.sel.hist[(k >> 8) & 0xfffu], 1u);
        }
        __syncthreads();
        int d2, g2;
        find_bin(s, k1, d2, g2);
        int k2 = k1 - g2;
        unsigned int P24 = ((unsigned int)d1 << 12) | (unsigned int)d2;
        __syncthreads();
        for (int i = t; i < 4096; i += NTH) s.u.sel.hist[i] = 0;
        __syncthreads();
        for (int n = t; n < NP; n += NTH) {
            unsigned int k = keys[n];
            if ((k >> 8) == P24) atomicAdd(&s.u.sel.hist[k & 0xffu], 1u);
        }
        __syncthreads();
        int d3, g3;
        find_bin(s, k2, d3, g3);
        int need = k2 - g3;
        unsigned int KP = (P24 << 8) | (unsigned int)d3;
        if (t == 0) s.s_cnt = 0;
        __syncthreads();
        for (int n = t; n < NP; n += NTH) {
            unsigned int k = keys[n];
            if ((int)(k >> 20) == d1 && k > KP) {
                unsigned int p = atomicAdd(&s.s_cnt, 1u);
                s.sortbuf[g1 + p] = packci(k, (unsigned int)n);
            }
        }
        __syncthreads();
        if (t < 32) {
            int taken = 0;
            int slot0 = g1 + (k1 - need);
            for (int base2 = 0; base2 < NP && taken < need; base2 += 32) {
                unsigned int k = keys[base2 + t];
                bool e = (k == KP);
                unsigned int bal = __ballot_sync(0xffffffffu, e);
                int rank = __popc(bal & ((1u << t) - 1u));
                if (e && taken + rank < need)
                    s.sortbuf[slot0 + taken + rank] = packci(KP, (unsigned int)(base2 + t));
                taken += __popc(bal);
            }
        }
    }
    __syncthreads();

    // ---------- fused sort1-rank + decode: exactly 400 entries = 25 full warps ----------
    if (t < 2 * TOPK) {
        int e = t >> 1;
        int p = t & 1;
        unsigned long long my = s.sortbuf[e];
        const ulonglong2* sb2 = reinterpret_cast<const ulonglong2*>(s.sortbuf) + p * 100;
        int rank = 0;
#pragma unroll 4
        for (int j = 0; j < 100; ++j) {
            ulonglong2 v = sb2[j];
            rank += (v.x > my) ? 1 : 0;
            rank += (v.y > my) ? 1 : 0;
        }
        rank += __shfl_xor_sync(0xffffffffu, rank, 1);
        if (p == 0) {
            unsigned int k = (unsigned int)(my >> 32);
            unsigned int idx = ~(unsigned int)my;
            float sc = ikey(k);
            float4 pr = reinterpret_cast<const float4*>(priors)[idx];
            const float* pp = pb + (size_t)idx * 6;
            float l0 = pp[0], l1 = pp[1], l2 = pp[2], l3 = pp[3];
            float c0 = pp[4], c1 = pp[5];
            float cx = pr.x + l0 * 0.1f * pr.z;
            float cy = pr.y + l1 * 0.1f * pr.w;
            float w  = pr.z * expf(l2 * 0.2f);
            float h  = pr.w * expf(l3 * 0.2f);
            float4 bx = make_float4(cx - 0.5f * w, cy - 0.5f * h, cx + 0.5f * w, cy + 0.5f * h);
            s.cbox[rank]  = bx;
            s.carea[rank] = (bx.z - bx.x) * (bx.w - bx.y);
            s.cscore[rank] = sc;
            s.clabel[rank] = (c1 > c0) ? 1.0f : 0.0f;
            if (!(sc > CONF_TH)) atomicOr(&s.keepw[rank >> 5], 1u << (rank & 31));
        }
    }
    __syncthreads();

    // ---------- suppression bit matrix: 2 rows per warp-pass ----------
    {
        int wi = t >> 5;
        int lane = t & 31;
        for (int ip = wi; ip < TOPK / 2; ip += 32) {
            int iA = 2 * ip, iB = iA + 1;
            float4 bA = s.cbox[iA]; float aA = s.carea[iA];
            float4 bB = s.cbox[iB]; float aB = s.carea[iB];
            int w0 = iA >> 5;
            for (int word = w0; word < 13; ++word) {
                int j = (word << 5) | lane;
                float4 bj = s.cbox[j];
                float aj = s.carea[j];
                // row A
                float iwA = fmaxf(fminf(bA.z, bj.z) - fmaxf(bA.x, bj.x), 0.0f);
                float ihA = fmaxf(fminf(bA.w, bj.w) - fmaxf(bA.y, bj.y), 0.0f);
                float inA = iwA * ihA;
                float ssA = aA + aj;
                float mA  = __fmaf_rn(3.0f, inA, -ssA);
                float tA  = 1e-4f * ssA + 1e-20f;
                bool supA;
                if (mA > tA)        supA = true;
                else if (mA >= -tA) supA = (inA / (ssA - inA + 1e-12f)) > NMS_TH;
                else                supA = false;
                // row B
                float iwB = fmaxf(fminf(bB.z, bj.z) - fmaxf(bB.x, bj.x), 0.0f);
                float ihB = fmaxf(fminf(bB.w, bj.w) - fmaxf(bB.y, bj.y), 0.0f);
                float inB = iwB * ihB;
                float ssB = aB + aj;
                float mB  = __fmaf_rn(3.0f, inB, -ssB);
                float tB  = 1e-4f * ssB + 1e-20f;
                bool supB;
                if (mB > tB)        supB = true;
                else if (mB >= -tB) supB = (inB / (ssB - inB + 1e-12f)) > NMS_TH;
                else                supB = false;
                unsigned int balA = __ballot_sync(0xffffffffu, supA);
                unsigned int balB = __ballot_sync(0xffffffffu, supB);
                if (lane == 0) {
                    s.u.sup[iA * 16 + word] = balA & rowmask(iA, word);
                    s.u.sup[iB * 16 + word] = balB & rowmask(iB, word);
                }
            }
        }
    }
    __syncthreads();

    // ---------- single-warp greedy NMS reduce (no block barriers inside) ----------
    if (t < 32) {
        int lane = t;
        unsigned int rm = (lane < 13) ? s.keepw[lane] : 0u;
#pragma unroll 1
        for (int g = 0; g < 13; ++g) {
            unsigned int m = __shfl_sync(0xffffffffu, rm, g);
            const unsigned int* rowg = &s.u.sup[(g * 32) * 16 + g];
#pragma unroll
            for (int ch = 0; ch < 4; ++ch) {
                unsigned int rr[8];
#pragma unroll
                for (int q = 0; q < 8; ++q) rr[q] = rowg[(ch * 8 + q) * 16];
#pragma unroll
                for (int q = 0; q < 8; ++q) {
                    int bb = ch * 8 + q;
                    if (!((m >> bb) & 1u)) m |= rr[q];
                }
            }
            if (lane > g && lane < 13) {
                unsigned int acc = 0;
                const unsigned int* col = &s.u.sup[(g * 32) * 16 + lane];
#pragma unroll
                for (int r = 0; r < 32; ++r) {
                    unsigned int v = col[r * 16];
                    acc |= ((m >> r) & 1u) ? 0u : v;
                }
                rm |= acc;
            }
            if (lane == g) rm = m;
        }
        if (lane < 13) s.keepw[lane] = rm;
    }
    __syncthreads();

    // ---------- output: kept-only compaction + warp-uniform pair-split ranking ----------
    if (t == 0) {
        unsigned int acc = 0;
#pragma unroll
        for (int w = 0; w < 13; ++w) { s.woff[w] = acc; acc += (unsigned)__popc(~s.keepw[w]); }
        s.s_mkept = acc;
    }
    __syncthreads();
    int mk = (int)s.s_mkept;
    if (t < TOPK) {
        bool kp = !((s.keepw[t >> 5] >> (t & 31)) & 1u);
        if (kp) {
            unsigned int before = (unsigned)__popc(~s.keepw[t >> 5] & ((1u << (t & 31)) - 1u));
            int pos = (int)(s.woff[t >> 5] + before);
            s.sortbuf[pos] = ((unsigned long long)__float_as_uint(s.cscore[t]) << 32) | (unsigned int)t;
        }
    }
    if (t < 512 && t >= mk) s.sortbuf[t] = 0xFFFFFFFFFFFFFFFFull;
    __syncthreads();
    {
        int tot2 = 2 * mk;                 // even -> lane pairs both active/inactive
        int tlim2 = (tot2 + 31) & ~31;     // warp-aligned participation
        if (t < tlim2) {
            int e = t >> 1;                 // e <= 415 < 512 (padded region valid)
            int p = t & 1;
            bool act = t < tot2;
            unsigned long long my = s.sortbuf[e];
            const ulonglong2* sb2 = reinterpret_cast<const ulonglong2*>(s.sortbuf);
            int vreal = (mk + 1) >> 1;
            int jmax = vreal - p * 128;
            jmax = jmax < 0 ? 0 : (jmax > 128 ? 128 : jmax);
            int rank = 0;
            for (int j = 0; j < jmax; ++j) {
                ulonglong2 v = sb2[p * 128 + j];
                rank += (v.x < my) ? 1 : 0;
                rank += (v.y < my) ? 1 : 0;
            }
            rank += __shfl_xor_sync(0xffffffffu, rank, 1);
            if (act && p == 0 && rank < KEEPK) {
                int c = (int)(unsigned int)(my & 0xffffffffu);
                float4 bx = s.cbox[c];
                float* o = out + ((size_t)b * KEEPK + rank) * 6;
                o[0] = s.clabel[c];
                o[1] = s.cscore[c];
                o[2] = bx.x; o[3] = bx.y; o[4] = bx.z; o[5] = bx.w;
            }
        }
    }
    if (t < KEEPK && t >= mk) {
        float* o = out + ((size_t)b * KEEPK + t) * 6;
        o[0] = 0.0f; o[1] = 0.0f; o[2] = 0.0f;
        o[3] = 0.0f; o[4] = 0.0f; o[5] = 0.0f;
    }
}

extern "C" void kernel_launch(void* const* d_in, const int* in_sizes, int n_in,
                              void* d_out, int out_size) {
    const float* pred = (const float*)d_in[0];
    const float* pri  = (const float*)d_in[1];
    if (n_in >= 2 && in_sizes[0] < in_sizes[1]) {
        const float* tmp = pred; pred = pri; pri = tmp;
    }
    float* out = (float*)d_out;
    int gridA = (NB * NP) / (NTH * APT);   // 512 blocks, 4 per image
    key_hist_kernel<<<gridA, NTH>>>(pred);
    box_selector_kernel<<<NB, NTH>>>(pred, pri, out);
}